// round 1
// baseline (speedup 1.0000x reference)
#include <cuda_runtime.h>
#include <cstdint>

#define D   512
#define TE  32
#define NT  256
#define KC  16

// scatter-sum scratch: agg[NG][D]
__device__ float g_agg[65536 * 512];

__device__ __forceinline__ unsigned long long pack2(float a) {
    unsigned long long r;
    asm("mov.b64 %0, {%1, %1};" : "=l"(r) : "r"(__float_as_uint(a)));
    return r;
}
__device__ __forceinline__ void fma2(float2& c, unsigned long long a2, float2 w) {
    unsigned long long cc = *reinterpret_cast<unsigned long long*>(&c);
    unsigned long long ww = *reinterpret_cast<unsigned long long*>(&w);
    asm("fma.rn.f32x2 %0, %1, %2, %0;" : "+l"(cc) : "l"(a2), "l"(ww));
    c = *reinterpret_cast<float2*>(&cc);
}
__device__ __forceinline__ float warp_sum(float v) {
#pragma unroll
    for (int o = 16; o; o >>= 1) v += __shfl_xor_sync(0xffffffffu, v, o);
    return v;
}
__device__ __forceinline__ float silu(float x) {
    return __fdividef(x, 1.0f + __expf(-x));
}

__device__ __forceinline__ void init_bias(float2 acc[4][8], const float* __restrict__ b, int tx) {
#pragma unroll
    for (int j = 0; j < 8; ++j) {
        float2 bb = *reinterpret_cast<const float2*>(&b[64 * j + 2 * tx]);
#pragma unroll
        for (int i = 0; i < 4; ++i) acc[i][j] = bb;
    }
}

// acc[i][j] covers row (wid*4+i), cols (64*j + 2*tx, +1)
template <class StageA, class ReadA>
__device__ __forceinline__ void gemm_acc(float2 acc[4][8], const float* __restrict__ W,
                                         int Ktot, float* sW, int tid, int wid, int tx,
                                         StageA stageA, ReadA readA) {
    for (int k0 = 0; k0 < Ktot; k0 += KC) {
        // stage W chunk [KC][D] -> shared (coalesced float4)
        const float4* Wg = reinterpret_cast<const float4*>(W + (size_t)k0 * D);
        float4* sW4 = reinterpret_cast<float4*>(sW);
#pragma unroll
        for (int m = 0; m < (KC * D / 4) / NT; ++m)
            sW4[tid + m * NT] = Wg[tid + m * NT];
        stageA(k0);
        __syncthreads();
#pragma unroll
        for (int kk = 0; kk < KC; ++kk) {
            unsigned long long a2[4];
#pragma unroll
            for (int i = 0; i < 4; ++i)
                a2[i] = pack2(readA(wid * 4 + i, k0 + kk, kk));
#pragma unroll
            for (int j = 0; j < 8; ++j) {
                float2 w = *reinterpret_cast<const float2*>(&sW[kk * D + 64 * j + 2 * tx]);
#pragma unroll
                for (int i = 0; i < 4; ++i) fma2(acc[i][j], a2[i], w);
            }
        }
        __syncthreads();
    }
}

__device__ __forceinline__ void silu_store(float2 acc[4][8], float* dst, int wid, int tx) {
#pragma unroll
    for (int i = 0; i < 4; ++i) {
        int r = wid * 4 + i;
#pragma unroll
        for (int j = 0; j < 8; ++j) {
            float2 v = acc[i][j];
            v.x = silu(v.x); v.y = silu(v.y);
            *reinterpret_cast<float2*>(&dst[r * D + 64 * j + 2 * tx]) = v;
        }
    }
}

__device__ __forceinline__ void layernorm(float2 acc[4][8], const float* __restrict__ g,
                                          const float* __restrict__ beta, int tx) {
#pragma unroll
    for (int i = 0; i < 4; ++i) {
        float s = 0.f, ss = 0.f;
#pragma unroll
        for (int j = 0; j < 8; ++j) {
            s  += acc[i][j].x + acc[i][j].y;
            ss += acc[i][j].x * acc[i][j].x + acc[i][j].y * acc[i][j].y;
        }
        s = warp_sum(s); ss = warp_sum(ss);
        float m    = s * (1.0f / D);
        float var  = ss * (1.0f / D) - m * m;
        float rstd = rsqrtf(var + 1e-5f);
#pragma unroll
        for (int j = 0; j < 8; ++j) {
            int c = 64 * j + 2 * tx;
            float2 gg = *reinterpret_cast<const float2*>(&g[c]);
            float2 bb = *reinterpret_cast<const float2*>(&beta[c]);
            acc[i][j].x = (acc[i][j].x - m) * rstd * gg.x + bb.x;
            acc[i][j].y = (acc[i][j].y - m) * rstd * gg.y + bb.y;
        }
    }
}

__global__ void zero_kernel(int n4) {
    int i = blockIdx.x * blockDim.x + threadIdx.x;
    if (i < n4) *reinterpret_cast<float4*>(&g_agg[(size_t)i * 4]) = make_float4(0.f, 0.f, 0.f, 0.f);
}

// Fused: emb MLP -> edge MLP -> residual -> atomic scatter into g_agg
__global__ void __launch_bounds__(NT, 1) edge_kernel(
    const float* __restrict__ gridf, const float* __restrict__ mesh,
    const int* __restrict__ eidx, const float* __restrict__ efeat,
    const float* __restrict__ embW0, const float* __restrict__ embb0,
    const float* __restrict__ embW1, const float* __restrict__ embb1,
    const float* __restrict__ embg,  const float* __restrict__ embbt,
    const float* __restrict__ edW0,  const float* __restrict__ edb0,
    const float* __restrict__ edW1,  const float* __restrict__ edb1,
    const float* __restrict__ edg,   const float* __restrict__ edbt,
    int E) {
    extern __shared__ float smem[];
    float* sE   = smem;               // TE*D : e after embedder
    float* sH   = sE + TE * D;        // TE*D : hidden buffer
    float* sW   = sH + TE * D;        // KC*D : weight staging
    float* sA   = sW + KC * D;        // TE*KC: gathered A staging
    int*   sIdx = reinterpret_cast<int*>(sA + TE * KC);   // [src x TE | dst x TE]
    float* sEf  = reinterpret_cast<float*>(sIdx + 2 * TE);// TE*4

    const int tid = threadIdx.x, wid = tid >> 5, tx = tid & 31;
    const int e0 = blockIdx.x * TE;

    if (tid < TE) {
        int e = min(e0 + tid, E - 1);
        sIdx[tid]      = eidx[e];       // src (mesh)
        sIdx[TE + tid] = eidx[E + e];   // dst (grid)
    }
    if (tid < TE * 4) {
        int e = min(e0 + (tid >> 2), E - 1);
        sEf[tid] = efeat[(size_t)e * 4 + (tid & 3)];
    }
    __syncthreads();

    float2 acc[4][8];

    // ---- phase 1: h = silu(ef @ embW0 + b0)  (K=4, weights from L1/L2) ----
    init_bias(acc, embb0, tx);
#pragma unroll
    for (int i = 0; i < 4; ++i) {
        int r = wid * 4 + i;
        float a0 = sEf[r * 4 + 0], a1 = sEf[r * 4 + 1];
        float a2 = sEf[r * 4 + 2], a3 = sEf[r * 4 + 3];
#pragma unroll
        for (int j = 0; j < 8; ++j) {
            int c = 64 * j + 2 * tx;
            float2 w0 = *reinterpret_cast<const float2*>(&embW0[0 * D + c]);
            float2 w1 = *reinterpret_cast<const float2*>(&embW0[1 * D + c]);
            float2 w2 = *reinterpret_cast<const float2*>(&embW0[2 * D + c]);
            float2 w3 = *reinterpret_cast<const float2*>(&embW0[3 * D + c]);
            acc[i][j].x += a0 * w0.x + a1 * w1.x + a2 * w2.x + a3 * w3.x;
            acc[i][j].y += a0 * w0.y + a1 * w1.y + a2 * w2.y + a3 * w3.y;
        }
    }
    silu_store(acc, sH, wid, tx);

    // ---- phase 2: e = LN(h @ embW1 + b1) -> sE ----
    init_bias(acc, embb1, tx);
    gemm_acc(acc, embW1, D, sW, tid, wid, tx,
             [](int) {},
             [&](int r, int k, int) { return sH[r * D + k]; });
    layernorm(acc, embg, embbt, tx);
#pragma unroll
    for (int i = 0; i < 4; ++i) {
        int r = wid * 4 + i;
#pragma unroll
        for (int j = 0; j < 8; ++j)
            *reinterpret_cast<float2*>(&sE[r * D + 64 * j + 2 * tx]) = acc[i][j];
    }

    // ---- phase 3: h = silu([e|mesh[src]|grid[dst]] @ edW0 + b0) ----
    init_bias(acc, edb0, tx);
    gemm_acc(acc, edW0, 3 * D, sW, tid, wid, tx,
             [&](int k0) {
                 if (k0 >= D) {
                     int row = tid >> 3, q = (tid & 7) * 2;
                     const float* src = (k0 < 2 * D)
                         ? mesh  + (size_t)sIdx[row]      * D + (k0 - D)     + q
                         : gridf + (size_t)sIdx[TE + row] * D + (k0 - 2 * D) + q;
                     *reinterpret_cast<float2*>(&sA[row * KC + q]) =
                         *reinterpret_cast<const float2*>(src);
                 }
             },
             [&](int r, int k, int kk) { return (k < D) ? sE[r * D + k] : sA[r * KC + kk]; });
    silu_store(acc, sH, wid, tx);

    // ---- phase 4: e_new = LN(h @ edW1 + b1) + e ; scatter-add to agg[dst] ----
    init_bias(acc, edb1, tx);
    gemm_acc(acc, edW1, D, sW, tid, wid, tx,
             [](int) {},
             [&](int r, int k, int) { return sH[r * D + k]; });
    layernorm(acc, edg, edbt, tx);
#pragma unroll
    for (int i = 0; i < 4; ++i) {
        int r = wid * 4 + i;
        if (e0 + r < E) {
            float* ap = g_agg + (size_t)sIdx[TE + r] * D;
#pragma unroll
            for (int j = 0; j < 8; ++j) {
                int c = 64 * j + 2 * tx;
                float2 e = *reinterpret_cast<const float2*>(&sE[r * D + c]);
                atomicAdd(ap + c,     acc[i][j].x + e.x);
                atomicAdd(ap + c + 1, acc[i][j].y + e.y);
            }
        }
    }
}

// Fused node MLP: out = LN(silu([grid|agg] @ nW0 + b0) @ nW1 + b1) + grid
__global__ void __launch_bounds__(NT, 1) node_kernel(
    const float* __restrict__ gridf,
    const float* __restrict__ nW0, const float* __restrict__ nb0,
    const float* __restrict__ nW1, const float* __restrict__ nb1,
    const float* __restrict__ ng,  const float* __restrict__ nbt,
    float* __restrict__ out, int NG) {
    extern __shared__ float smem[];
    float* sH = smem;            // TE*D
    float* sW = sH + TE * D;     // KC*D
    float* sA = sW + KC * D;     // TE*KC

    const int tid = threadIdx.x, wid = tid >> 5, tx = tid & 31;
    const int n0 = blockIdx.x * TE;

    float2 acc[4][8];
    init_bias(acc, nb0, tx);
    gemm_acc(acc, nW0, 2 * D, sW, tid, wid, tx,
             [&](int k0) {
                 int row = tid >> 3, q = (tid & 7) * 2;
                 int nr = min(n0 + row, NG - 1);
                 const float* src = (k0 < D)
                     ? gridf + (size_t)nr * D + k0       + q
                     : g_agg + (size_t)nr * D + (k0 - D) + q;
                 *reinterpret_cast<float2*>(&sA[row * KC + q]) =
                     *reinterpret_cast<const float2*>(src);
             },
             [&](int r, int, int kk) { return sA[r * KC + kk]; });
    silu_store(acc, sH, wid, tx);

    init_bias(acc, nb1, tx);
    gemm_acc(acc, nW1, D, sW, tid, wid, tx,
             [](int) {},
             [&](int r, int k, int) { return sH[r * D + k]; });
    layernorm(acc, ng, nbt, tx);

#pragma unroll
    for (int i = 0; i < 4; ++i) {
        int r = wid * 4 + i;
        if (n0 + r < NG) {
            size_t base = (size_t)(n0 + r) * D;
#pragma unroll
            for (int j = 0; j < 8; ++j) {
                int c = 64 * j + 2 * tx;
                float2 gr = *reinterpret_cast<const float2*>(&gridf[base + c]);
                float2 v;
                v.x = acc[i][j].x + gr.x;
                v.y = acc[i][j].y + gr.y;
                *reinterpret_cast<float2*>(&out[base + c]) = v;
            }
        }
    }
}

extern "C" void kernel_launch(void* const* d_in, const int* in_sizes, int n_in,
                              void* d_out, int out_size) {
    const float* gridf = (const float*)d_in[0];
    const float* mesh  = (const float*)d_in[1];
    const int*   eidx  = (const int*)  d_in[2];
    const float* efeat = (const float*)d_in[3];
    const float* embW0 = (const float*)d_in[4];
    const float* embb0 = (const float*)d_in[5];
    const float* embW1 = (const float*)d_in[6];
    const float* embb1 = (const float*)d_in[7];
    const float* embg  = (const float*)d_in[8];
    const float* embbt = (const float*)d_in[9];
    const float* edW0  = (const float*)d_in[10];
    const float* edb0  = (const float*)d_in[11];
    const float* edW1  = (const float*)d_in[12];
    const float* edb1  = (const float*)d_in[13];
    const float* edg   = (const float*)d_in[14];
    const float* edbt  = (const float*)d_in[15];
    const float* ndW0  = (const float*)d_in[16];
    const float* ndb0  = (const float*)d_in[17];
    const float* ndW1  = (const float*)d_in[18];
    const float* ndb1  = (const float*)d_in[19];
    const float* ndg   = (const float*)d_in[20];
    const float* ndbt  = (const float*)d_in[21];
    float* out = (float*)d_out;

    const int NG = in_sizes[0] / D;
    const int E  = in_sizes[2] / 2;

    const int smemE = (2 * TE * D + KC * D + TE * KC) * 4 + 2 * TE * 4 + TE * 4 * 4;
    const int smemN = (TE * D + KC * D + TE * KC) * 4;
    cudaFuncSetAttribute(edge_kernel, cudaFuncAttributeMaxDynamicSharedMemorySize, smemE);
    cudaFuncSetAttribute(node_kernel, cudaFuncAttributeMaxDynamicSharedMemorySize, smemN);

    int n4 = NG * D / 4;
    zero_kernel<<<(n4 + NT - 1) / NT, NT>>>(n4);
    edge_kernel<<<(E + TE - 1) / TE, NT, smemE>>>(
        gridf, mesh, eidx, efeat,
        embW0, embb0, embW1, embb1, embg, embbt,
        edW0, edb0, edW1, edb1, edg, edbt, E);
    node_kernel<<<(NG + TE - 1) / TE, NT, smemN>>>(
        gridf, ndW0, ndb0, ndW1, ndb1, ndg, ndbt, out, NG);
}